// round 1
// baseline (speedup 1.0000x reference)
#include <cuda_runtime.h>
#include <cstdint>

#define RR 8192
#define NX 32
#define NM 64
#define WST 97            // 32 (M) + 32 (-ap) + 1 (w) + 32 (I)
#define FW_S 32
#define FW_W 96
#define FW_BLOCKS (RR/FW_S)   // 256
#define BW_S 64
#define BW_W 96
#define BW_BLOCKS (RR/BW_S)   // 128
#define NT 512

// Scratch: forward pass products consumed by backward pass.
// g_linvT[r][i][j] = (L_r^{-1})[j][i]  (transposed L-inverse, row-major)
// g_offT [r][k][i] = off_r[i][k]       (i.e. Y = L^{-1}(-ap), row-major)
__device__ float g_linvT[RR*NX*NX];
__device__ float g_offT [RR*NX*NX];
__device__ float g_u    [RR*NX];

// ---------------------------------------------------------------------------
// Forward: chunked scan with warm-up. Augmented LDL^T elimination fuses
// Cholesky + solve(L, -ap) + solve(L, w) + explicit L^{-1} in one sweep.
// ---------------------------------------------------------------------------
__global__ __launch_bounds__(NT) void fwd_kernel(
    const float* __restrict__ hess, const float* __restrict__ grads,
    const float* __restrict__ Amat, const float* __restrict__ Ptp,
    const float* __restrict__ Pinit)
{
    __shared__ float W[NX*WST];
    __shared__ float pred[NX*33];
    __shared__ float offT[NX*33];
    __shared__ float ap_s[NX*33];
    __shared__ float apat_s[NX*33];
    __shared__ float P_s[NX*33];
    __shared__ float A_s[NX*33];
    __shared__ float u_s[NX];
    __shared__ float rstd_s[NX];

    const int tid = threadIdx.x;
    const int b   = blockIdx.x;
    int r0 = b*FW_S - FW_W; if (r0 < 0) r0 = 0;
    const int rend  = (b+1)*FW_S;
    const int rmain = b*FW_S;
    const int nsteps = rend - r0;
    const bool exact = (r0 == 0);   // exact init chain (no approximation)

    // Load constants, init carry (pred = Pinit exact, else guess Ptp; off=0, u=0)
    for (int idx = tid; idx < NX*NX; idx += NT) {
        int i = idx >> 5, j = idx & 31;
        A_s [i*33+j] = Amat[idx];
        P_s [i*33+j] = Ptp[idx];
        pred[i*33+j] = exact ? Pinit[idx] : Ptp[idx];
        offT[i*33+j] = 0.f;
    }
    if (tid < NX) u_s[tid] = 0.f;
    __syncthreads();
    // ap = A @ Ptp
    for (int idx = tid; idx < NX*NX; idx += NT) {
        int i = idx >> 5, j = idx & 31;
        float s = 0.f;
        #pragma unroll
        for (int k = 0; k < NX; k++) s += A_s[i*33+k]*P_s[k*33+j];
        ap_s[i*33+j] = s;
    }
    __syncthreads();
    // apat = ap @ A^T
    for (int idx = tid; idx < NX*NX; idx += NT) {
        int i = idx >> 5, j = idx & 31;
        float s = 0.f;
        #pragma unroll
        for (int k = 0; k < NX; k++) s += ap_s[i*33+k]*A_s[j*33+k];
        apat_s[i*33+j] = s;
    }
    __syncthreads();

    const int i0 = tid >> 5;   // 0..15
    const int j0 = tid & 31;

    // register prefetch of hess / grad for first step
    float h0 = hess[(size_t)r0*1024 + tid];
    float h1 = hess[(size_t)r0*1024 + 512 + tid];
    float gpre = (tid < NX) ? grads[r0*NX + tid] : 0.f;

    for (int step = 0; step < nsteps; step++) {
        const int r = r0 + step;
        const float mfac = (r == RR-1) ? 0.f : 1.f;

        // ---- build augmented W = [pred+hess+m*apat | -ap | w | I] ----
        W[i0*WST + j0]          = pred[i0*33+j0]      + h0 + mfac*apat_s[i0*33+j0];
        W[(i0+16)*WST + j0]     = pred[(i0+16)*33+j0] + h1 + mfac*apat_s[(i0+16)*33+j0];
        W[i0*WST + 32 + j0]     = -ap_s[i0*33+j0];
        W[(i0+16)*WST + 32 + j0]= -ap_s[(i0+16)*33+j0];
        W[i0*WST + 65 + j0]     = (i0 == j0) ? 1.f : 0.f;
        W[(i0+16)*WST + 65 + j0]= ((i0+16) == j0) ? 1.f : 0.f;
        if (tid < NX) {   // w = grad - u @ off^T   (uses previous step's off, u)
            float wv = gpre;
            #pragma unroll
            for (int k = 0; k < NX; k++) wv -= u_s[k]*offT[k*33 + tid];
            W[tid*WST + 64] = wv;
        }
        // prefetch next step's hess/grad (LDG latency hidden under elimination)
        if (step + 1 < nsteps) {
            h0 = hess[(size_t)(r+1)*1024 + tid];
            h1 = hess[(size_t)(r+1)*1024 + 512 + tid];
            if (tid < NX) gpre = grads[(r+1)*NX + tid];
        }
        __syncthreads();

        // ---- LDL^T elimination, one sync per pivot ----
        const int irow  = tid >> 4;   // 0..31 (row group)
        const int clane = tid & 15;   // 16 lanes across columns
        for (int k = 0; k < NX; k++) {
            const float inv_d = __frcp_rn(W[k*WST + k]);
            const int i = k + 1 + irow;
            if (i < NX) {
                const float lik = W[i*WST + k] * inv_d;
                for (int c = k + 1 + clane; c < WST; c += 16)
                    W[i*WST + c] -= lik * W[k*WST + c];
            }
            __syncthreads();
        }
        if (tid < NX) rstd_s[tid] = __frsqrt_rn(W[tid*WST + tid]);
        __syncthreads();

        const bool mainrow = (r >= rmain);
        const size_t rbase = (size_t)r * (NX*NX);

        // off^T rows (Y = L^{-1}(-ap)): offT[k][i] = W[k][32+i] * rstd[k]
        #pragma unroll
        for (int t = 0; t < 2; t++) {
            const int k = i0 + 16*t;
            const float ov = W[k*WST + 32 + j0] * rstd_s[k];
            offT[k*33 + j0] = ov;
            if (mainrow) g_offT[rbase + k*NX + j0] = ov;
        }
        // L^{-1} transposed store: g_linvT[r][c][k] = Linv[k][c]
        if (mainrow) {
            #pragma unroll
            for (int t = 0; t < 2; t++) {
                const int c = i0 + 16*t;    // Linv column
                const int k = j0;           // Linv row (lane: stride-97 smem, coalesced STG)
                g_linvT[rbase + c*NX + k] = W[k*WST + 65 + c] * rstd_s[k];
            }
        }
        // u' = (L^{-1} w)^T
        if (tid < NX) {
            const float un = W[tid*WST + 64] * rstd_s[tid];
            u_s[tid] = un;
            if (mainrow) g_u[r*NX + tid] = un;
        }
        __syncthreads();

        // pred' = P - off off^T = P - offT^T offT
        #pragma unroll
        for (int t = 0; t < 2; t++) {
            const int i = i0 + 16*t;
            float s = P_s[i*33 + j0];
            #pragma unroll
            for (int k = 0; k < NX; k++) s -= offT[k*33 + i] * offT[k*33 + j0];
            pred[i*33 + j0] = s;
        }
        __syncthreads();
    }
}

// ---------------------------------------------------------------------------
// Backward: chunked reverse scan with warm-up. Pure dense matmuls per step:
//   tmp = g - vw @ off ;  vw = tmp @ Linv   (Linv stored transposed)
// 16 KB/step register-prefetched (double-buffered through registers).
// ---------------------------------------------------------------------------
__global__ __launch_bounds__(NT) void bwd_kernel(
    const float* __restrict__ epsx, float* __restrict__ out)
{
    __shared__ float vw  [65*33];
    __shared__ float tmp [65*33];
    __shared__ float linvT[NX*33];
    __shared__ float offt [NX*33];
    __shared__ float ebuf [NM*NX];   // stride 32 (row-wise reads only)
    __shared__ float u_row[NX];

    const int tid = threadIdx.x;
    const int b   = blockIdx.x;
    const int rlow     = b*BW_S;
    const int rmainTop = rlow + BW_S - 1;
    int rtop = rmainTop + BW_W; if (rtop > RR-1) rtop = RR-1;  // clamp = exact init
    const int nsteps = rtop - rlow + 1;

    for (int idx = tid; idx < 65*33; idx += NT) vw[idx] = 0.f;

    float4 lo4, ev4; float uva = 0.f;
    {   // initial prefetch
        const size_t rb = (size_t)rtop * 1024;
        if (tid < 256) lo4 = reinterpret_cast<const float4*>(g_linvT + rb)[tid];
        else           lo4 = reinterpret_cast<const float4*>(g_offT  + rb)[tid - 256];
        ev4 = reinterpret_cast<const float4*>(epsx + (size_t)rtop*2048)[tid];
        if (tid < 32) uva = g_u[rtop*NX + tid];
    }
    __syncthreads();

    for (int step = 0; step < nsteps; step++) {
        const int r = rtop - step;

        // stage prefetched tiles into padded smem
        if (tid < 256) {
            const int idx = tid*4, i = idx >> 5, c = idx & 31;
            float* p = &linvT[i*33 + c];
            p[0]=lo4.x; p[1]=lo4.y; p[2]=lo4.z; p[3]=lo4.w;
        } else {
            const int idx = (tid-256)*4, i = idx >> 5, c = idx & 31;
            float* p = &offt[i*33 + c];
            p[0]=lo4.x; p[1]=lo4.y; p[2]=lo4.z; p[3]=lo4.w;
        }
        {
            float* p = &ebuf[tid*4];
            p[0]=ev4.x; p[1]=ev4.y; p[2]=ev4.z; p[3]=ev4.w;
        }
        if (tid < 32) u_row[tid] = uva;

        // prefetch next (latency hidden under the two matmul phases)
        if (step + 1 < nsteps) {
            const size_t rb = (size_t)(r-1) * 1024;
            if (tid < 256) lo4 = reinterpret_cast<const float4*>(g_linvT + rb)[tid];
            else           lo4 = reinterpret_cast<const float4*>(g_offT  + rb)[tid - 256];
            ev4 = reinterpret_cast<const float4*>(epsx + (size_t)(r-1)*2048)[tid];
            if (tid < 32) uva = g_u[(r-1)*NX + tid];
        }
        __syncthreads();

        // phase 1: tmp[m][j] = g[m][j] - sum_i vw[m][i] * off[i][j]
        for (int idx = tid; idx < 65*NX; idx += NT) {
            const int m = idx >> 5, j = idx & 31;
            float s = (m == 0) ? u_row[j] : ebuf[(m-1)*NX + j];
            #pragma unroll
            for (int i = 0; i < NX; i++) s -= vw[m*33 + i] * offt[j*33 + i];
            tmp[m*33 + j] = s;
        }
        __syncthreads();

        // phase 2: vw[m][i] = sum_j tmp[m][j] * Linv[j][i]  (= tmp @ Linv)
        for (int idx = tid; idx < 65*NX; idx += NT) {
            const int m = idx >> 5, i = idx & 31;
            float s = 0.f;
            #pragma unroll
            for (int j = 0; j < NX; j++) s += tmp[m*33 + j] * linvT[i*33 + j];
            vw[m*33 + i] = s;
        }
        __syncthreads();

        // output: out[r][m][i] = vs + ws = vw[0][i] + vw[m+1][i]
        if (r <= rmainTop) {
            float* orow = out + (size_t)r * (NM*NX);
            for (int idx = tid; idx < NM*NX; idx += NT) {
                const int m = idx >> 5, i = idx & 31;
                orow[idx] = vw[i] + vw[(m+1)*33 + i];
            }
        }
        __syncthreads();
    }
}

extern "C" void kernel_launch(void* const* d_in, const int* in_sizes, int n_in,
                              void* d_out, int out_size) {
    const float* hess  = (const float*)d_in[0];   // (8192,32,32)
    const float* grads = (const float*)d_in[1];   // (8192,1,32)
    const float* Amat  = (const float*)d_in[2];   // (32,32)
    const float* Ptp   = (const float*)d_in[3];   // (32,32)
    const float* Pinit = (const float*)d_in[4];   // (32,32)
    const float* epsx  = (const float*)d_in[5];   // (8192,64,32)
    float* out = (float*)d_out;                   // (8192,64,32)
    (void)in_sizes; (void)n_in; (void)out_size;

    fwd_kernel<<<FW_BLOCKS, NT>>>(hess, grads, Amat, Ptp, Pinit);
    bwd_kernel<<<BW_BLOCKS, NT>>>(epsx, out);
}